// round 1
// baseline (speedup 1.0000x reference)
#include <cuda_runtime.h>

// Scratch: channel-last copies of all 4 img tensors.
// sum over scales of B*H*W*C = 16*16*(512^2+256^2+128^2+64^2) = 89,128,960 floats.
__device__ float g_timg[89128960];

// ---------------------------------------------------------------------------
// Transpose [B,C,H,W] -> [B,H,W,C], C=16. Block handles (b, i, 32-wide j tile).
// blockDim = (32,16): ty = channel, tx = j offset. Coalesced load + store.
// ---------------------------------------------------------------------------
__global__ void transpose_cl_kernel(const float* __restrict__ img,
                                    size_t timg_off, int H, int W) {
    __shared__ float s[16][33];
    const int b  = blockIdx.z;
    const int i  = blockIdx.y;
    const int j0 = blockIdx.x * 32;
    const int tx = threadIdx.x;   // 0..31 (j within tile)
    const int ty = threadIdx.y;   // 0..15 (channel)

    const size_t HW = (size_t)H * W;
    s[ty][tx] = img[((size_t)b * 16 + ty) * HW + (size_t)i * W + (j0 + tx)];
    __syncthreads();

    // flat write: idx -> (w_local = idx/16, c = idx%16), contiguous global addrs
    const int idx = ty * 32 + tx;
    const int wl  = idx >> 4;
    const int c   = idx & 15;
    float* timg = g_timg + timg_off;
    timg[((size_t)b * HW + (size_t)i * W + (j0 + wl)) * 16 + c] = s[c][wl];
}

// ---------------------------------------------------------------------------
// Warp kernel: one thread per output pixel (b,i,j), all 16 channels.
// x = (i-1) + flow0*0.5*(W-1)   (width coord, per reference's channel mapping)
// y = (j-1) + flow1*0.5*(H-1)   (height coord)
// Bilinear, zero padding, align_corners=True semantics.
// ---------------------------------------------------------------------------
__global__ void warp_gather_kernel(const float* __restrict__ flow,
                                   size_t timg_off,
                                   float* __restrict__ out,
                                   int H, int W) {
    const int t = blockIdx.x * blockDim.x + threadIdx.x;
    const size_t HW = (size_t)H * W;
    const int j   = t % W;
    const int tmp = t / W;
    const int i   = tmp % H;
    const int b   = tmp / H;

    const float f0 = flow[((size_t)b * 2 + 0) * HW + (size_t)i * W + j];
    const float f1 = flow[((size_t)b * 2 + 1) * HW + (size_t)i * W + j];

    const float sc = 0.5f * (float)(W - 1);
    const float x = (float)(i - 1) + f0 * sc;   // width coord
    const float y = (float)(j - 1) + f1 * sc;   // height coord

    const float x0f = floorf(x);
    const float y0f = floorf(y);
    const float wx1 = x - x0f, wx0 = 1.0f - wx1;
    const float wy1 = y - y0f, wy0 = 1.0f - wy1;
    const int x0 = (int)x0f;
    const int y0 = (int)y0f;

    const float* timg = g_timg + timg_off;

    float acc[16];
#pragma unroll
    for (int c = 0; c < 16; c++) acc[c] = 0.0f;

#pragma unroll
    for (int k = 0; k < 4; k++) {
        const int yy = y0 + (k >> 1);
        const int xx = x0 + (k & 1);
        const float w = ((k >> 1) ? wy1 : wy0) * ((k & 1) ? wx1 : wx0);
        if (yy >= 0 && yy < H && xx >= 0 && xx < W) {
            const float4* p = reinterpret_cast<const float4*>(
                timg + (((size_t)b * H + yy) * W + xx) * 16);
#pragma unroll
            for (int q = 0; q < 4; q++) {
                const float4 v = __ldg(p + q);
                acc[q * 4 + 0] = fmaf(w, v.x, acc[q * 4 + 0]);
                acc[q * 4 + 1] = fmaf(w, v.y, acc[q * 4 + 1]);
                acc[q * 4 + 2] = fmaf(w, v.z, acc[q * 4 + 2]);
                acc[q * 4 + 3] = fmaf(w, v.w, acc[q * 4 + 3]);
            }
        }
    }

    // out layout [B,C,H,W]; per-c writes are warp-coalesced along j.
    const size_t pix = (size_t)i * W + j;
#pragma unroll
    for (int c = 0; c < 16; c++) {
        out[((size_t)b * 16 + c) * HW + pix] = acc[c];
    }
}

// ---------------------------------------------------------------------------
// Launch: per scale, transpose img to channel-last scratch, then gather-warp.
// Inputs (metadata order): img0, flow0, img1, flow1, img2, flow2, img3, flow3.
// Output: concat(out0, out1, out2, out3), each [B,16,s,s] fp32.
// ---------------------------------------------------------------------------
extern "C" void kernel_launch(void* const* d_in, const int* in_sizes, int n_in,
                              void* d_out, int out_size) {
    (void)in_sizes; (void)n_in; (void)out_size;
    const int sizes[4] = {512, 256, 128, 64};
    float* out = (float*)d_out;

    size_t toff = 0;   // offset into g_timg (elements)
    size_t ooff = 0;   // offset into out (elements)

    for (int s = 0; s < 4; s++) {
        const int H = sizes[s], W = sizes[s];
        const float* img  = (const float*)d_in[2 * s];
        const float* flow = (const float*)d_in[2 * s + 1];

        dim3 tb(32, 16);
        dim3 tg(W / 32, H, 16);
        transpose_cl_kernel<<<tg, tb>>>(img, toff, H, W);

        const int total = 16 * H * W;  // B * H * W, divisible by 256 for all s
        warp_gather_kernel<<<total / 256, 256>>>(flow, toff, out + ooff, H, W);

        toff += (size_t)16 * H * W * 16;  // B*H*W*C
        ooff += (size_t)16 * 16 * H * W;  // B*C*H*W
    }
}

// round 2
// speedup vs baseline: 1.4670x; 1.4670x over previous
#include <cuda_runtime.h>
#include <cuda_fp16.h>

// Channel-last fp16 copies of all 4 img tensors.
// Element counts (== offsets below): 512: 67,108,864 | 256: 16,777,216 |
// 128: 4,194,304 | 64: 1,048,576. Total 89,128,960 halfs.
__device__ __half g_timg[89128960];

// ---------------------------------------------------------------------------
// Mega-transpose: [B,C,H,W] fp32 -> [B,H,W,C] fp16, C=16, all 4 scales in one
// grid. Block = (32,16), handles (b, i, 64-wide j tile) of one scale.
// Block counts: 512:65536 | 256:16384 | 128:4096 | 64:1024 -> cum 87040.
// ---------------------------------------------------------------------------
__global__ void transpose_all(const float* __restrict__ im0,
                              const float* __restrict__ im1,
                              const float* __restrict__ im2,
                              const float* __restrict__ im3) {
    __shared__ float s[16][65];
    unsigned bx = blockIdx.x;
    const float* img; unsigned lg; size_t toff;
    if (bx < 65536u)      { img = im0; lg = 9; toff = 0ull; }
    else if (bx < 81920u) { img = im1; lg = 8; toff = 67108864ull; bx -= 65536u; }
    else if (bx < 86016u) { img = im2; lg = 7; toff = 83886080ull; bx -= 81920u; }
    else                  { img = im3; lg = 6; toff = 88080384ull; bx -= 86016u; }

    const unsigned W   = 1u << lg;
    const unsigned tpr = lg - 6u;                 // log2(tiles per row), W/64
    const unsigned jt  = bx & ((1u << tpr) - 1u);
    const unsigned r   = bx >> tpr;
    const unsigned i   = r & (W - 1u);
    const unsigned b   = r >> lg;
    const unsigned j0  = jt << 6;
    const unsigned tx  = threadIdx.x, ty = threadIdx.y;
    const size_t   HW  = (size_t)1 << (2u * lg);

    const float* src = img + (size_t)(b * 16u + ty) * HW + (size_t)i * W + j0;
    s[ty][tx]       = src[tx];
    s[ty][tx + 32u] = src[tx + 32u];
    __syncthreads();

    // 512 threads write 512 half2 (64 pixels x 8 channel-pairs), coalesced.
    const unsigned idx = ty * 32u + tx;
    const unsigned wl  = idx >> 3;     // pixel within tile, 0..63
    const unsigned c2  = idx & 7u;     // channel pair, 0..7
    __half2 h = __floats2half2_rn(s[2u * c2][wl], s[2u * c2 + 1u][wl]);
    __half2* dst = reinterpret_cast<__half2*>(g_timg + toff);
    dst[((size_t)b * HW + (size_t)i * W + (j0 + wl)) * 8u + c2] = h;
}

// ---------------------------------------------------------------------------
// Mega-gather: 2 threads per output pixel (8 channels each). Each corner read
// is one 16B LDG; pair-threads (adjacent lanes) cover a full 32B sector.
// Coordinate math identical to the verified R1 kernel:
//   x = (i-1) + flow_ch0 * 0.5*(W-1)   (width coord)
//   y = (j-1) + flow_ch1 * 0.5*(H-1)   (height coord)
// Block counts (256 thr): 512:32768 | 256:8192 | 128:2048 | 64:512 -> cum 43520.
// ---------------------------------------------------------------------------
__global__ void gather_all(const float* __restrict__ fl0,
                           const float* __restrict__ fl1,
                           const float* __restrict__ fl2,
                           const float* __restrict__ fl3,
                           float* __restrict__ out) {
    unsigned bx = blockIdx.x;
    const float* flow; unsigned lg; size_t toff, ooff;
    if (bx < 32768u)      { flow = fl0; lg = 9; toff = 0ull;         ooff = 0ull; }
    else if (bx < 40960u) { flow = fl1; lg = 8; toff = 67108864ull; ooff = 67108864ull; bx -= 32768u; }
    else if (bx < 43008u) { flow = fl2; lg = 7; toff = 83886080ull; ooff = 83886080ull; bx -= 40960u; }
    else                  { flow = fl3; lg = 6; toff = 88080384ull; ooff = 88080384ull; bx -= 43008u; }

    const unsigned t     = bx * 256u + threadIdx.x;
    const unsigned chalf = t & 1u;       // which 8-channel half
    const unsigned p     = t >> 1;       // pixel index within scale
    const unsigned W     = 1u << lg;
    const unsigned HW    = 1u << (2u * lg);
    const unsigned j     = p & (W - 1u);
    const unsigned i     = (p >> lg) & (W - 1u);
    const unsigned b     = p >> (2u * lg);

    const float f0 = flow[(size_t)(b * 2u + 0u) * HW + (size_t)i * W + j];
    const float f1 = flow[(size_t)(b * 2u + 1u) * HW + (size_t)i * W + j];

    const float sc = 0.5f * (float)(W - 1u);
    const float x = (float)((int)i - 1) + f0 * sc;   // width coord
    const float y = (float)((int)j - 1) + f1 * sc;   // height coord

    const float x0f = floorf(x);
    const float y0f = floorf(y);
    const float wx1 = x - x0f, wx0 = 1.0f - wx1;
    const float wy1 = y - y0f, wy0 = 1.0f - wy1;
    const int x0 = (int)x0f;
    const int y0 = (int)y0f;
    const int Hs = (int)W;   // square images

    const __half2* timg2 = reinterpret_cast<const __half2*>(g_timg + toff);

    float acc[8];
#pragma unroll
    for (int q = 0; q < 8; q++) acc[q] = 0.0f;

#pragma unroll
    for (int k = 0; k < 4; k++) {
        const int yy = y0 + (k >> 1);
        const int xx = x0 + (k & 1);
        const float w = ((k >> 1) ? wy1 : wy0) * ((k & 1) ? wx1 : wx0);
        if (yy >= 0 && yy < Hs && xx >= 0 && xx < (int)W) {
            const size_t pix = (size_t)b * HW + (size_t)(unsigned)yy * W + (unsigned)xx;
            const uint4 raw = *reinterpret_cast<const uint4*>(timg2 + pix * 8u + chalf * 4u);
            const unsigned rw[4] = {raw.x, raw.y, raw.z, raw.w};
#pragma unroll
            for (int q = 0; q < 4; q++) {
                const __half2 h  = *reinterpret_cast<const __half2*>(&rw[q]);
                const float2  v  = __half22float2(h);
                acc[2 * q + 0] = fmaf(w, v.x, acc[2 * q + 0]);
                acc[2 * q + 1] = fmaf(w, v.y, acc[2 * q + 1]);
            }
        }
    }

    // out layout [B,C,H,W]; this thread's channels are [chalf*8, chalf*8+8).
    const size_t obase = ooff + (size_t)b * 16u * HW + (size_t)i * W + j;
#pragma unroll
    for (int q = 0; q < 8; q++) {
        out[obase + (size_t)(chalf * 8u + q) * HW] = acc[q];
    }
}

// ---------------------------------------------------------------------------
// Two launches total: mega-transpose (all scales) then mega-gather.
// Inputs (metadata order): img0, flow0, img1, flow1, img2, flow2, img3, flow3.
// ---------------------------------------------------------------------------
extern "C" void kernel_launch(void* const* d_in, const int* in_sizes, int n_in,
                              void* d_out, int out_size) {
    (void)in_sizes; (void)n_in; (void)out_size;
    const float* im0 = (const float*)d_in[0];
    const float* fl0 = (const float*)d_in[1];
    const float* im1 = (const float*)d_in[2];
    const float* fl1 = (const float*)d_in[3];
    const float* im2 = (const float*)d_in[4];
    const float* fl2 = (const float*)d_in[5];
    const float* im3 = (const float*)d_in[6];
    const float* fl3 = (const float*)d_in[7];
    float* out = (float*)d_out;

    transpose_all<<<87040, dim3(32, 16)>>>(im0, im1, im2, im3);
    gather_all<<<43520, 256>>>(fl0, fl1, fl2, fl3, out);
}

// round 3
// speedup vs baseline: 2.4253x; 1.6532x over previous
#include <cuda_runtime.h>
#include <cuda_fp16.h>

// Channel-last fp16 copies of all 4 img tensors.
// Half-element offsets: s512: 0 | s256: 67,108,864 | s128: 83,886,080 |
// s64: 88,080,384. Total 89,128,960 halfs.
__device__ __half g_timg[89128960];

// Shared block-dispatch table (256 threads/block, 2 threads per pixel):
//   scale 512: blocks [0, 32768)
//   scale 256: blocks [32768, 40960)
//   scale 128: blocks [40960, 43008)
//   scale  64: blocks [43008, 43520)

// ---------------------------------------------------------------------------
// Transpose [B,C,H,W] fp32 -> [B,H,W,C] fp16, no shared memory.
// Thread t -> (pixel p = t>>1, channel group g = t&1). 8 strided coalesced
// 32-bit loads (64B/warp each, full sectors), one coalesced 16B store.
// ---------------------------------------------------------------------------
__global__ void transpose_all(const float* __restrict__ im0,
                              const float* __restrict__ im1,
                              const float* __restrict__ im2,
                              const float* __restrict__ im3) {
    unsigned bx = blockIdx.x;
    const float* img; unsigned lg; size_t toff;
    if (bx < 32768u)      { img = im0; lg = 9; toff = 0ull; }
    else if (bx < 40960u) { img = im1; lg = 8; toff = 67108864ull; bx -= 32768u; }
    else if (bx < 43008u) { img = im2; lg = 7; toff = 83886080ull; bx -= 40960u; }
    else                  { img = im3; lg = 6; toff = 88080384ull; bx -= 43008u; }

    const unsigned t  = bx * 256u + threadIdx.x;
    const unsigned g  = t & 1u;            // channel group (0: ch0-7, 1: ch8-15)
    const unsigned p  = t >> 1;            // flat pixel within scale: b*HW + i*W + j
    const size_t   HW = (size_t)1 << (2u * lg);
    const unsigned b  = p >> (2u * lg);

    // img[(b*16 + c)*HW + pixoff] = img[p + b*15*HW + c*HW]
    const float* src = img + (size_t)p + (size_t)b * 15u * HW + (size_t)(g * 8u) * HW;

    float v[8];
#pragma unroll
    for (int k = 0; k < 8; k++) v[k] = src[(size_t)k * HW];

    uint4 o;
    __half2 h0 = __floats2half2_rn(v[0], v[1]);
    __half2 h1 = __floats2half2_rn(v[2], v[3]);
    __half2 h2 = __floats2half2_rn(v[4], v[5]);
    __half2 h3 = __floats2half2_rn(v[6], v[7]);
    o.x = *reinterpret_cast<unsigned*>(&h0);
    o.y = *reinterpret_cast<unsigned*>(&h1);
    o.z = *reinterpret_cast<unsigned*>(&h2);
    o.w = *reinterpret_cast<unsigned*>(&h3);

    // dst halfs at p*16 + g*8 == 8*t -> uint4 index t: perfectly coalesced.
    reinterpret_cast<uint4*>(g_timg + toff)[t] = o;
}

// ---------------------------------------------------------------------------
// Branchless gather: 2 threads per output pixel (8 channels each).
// Corner indices clamped; OOB validity folded into the bilinear weights;
// all 4 corner LDG.128 issued unconditionally (MLP=4).
//   x = (i-1) + flow_ch0 * 0.5*(W-1)   (width coord)
//   y = (j-1) + flow_ch1 * 0.5*(H-1)   (height coord)
// ---------------------------------------------------------------------------
__global__ void gather_all(const float* __restrict__ fl0,
                           const float* __restrict__ fl1,
                           const float* __restrict__ fl2,
                           const float* __restrict__ fl3,
                           float* __restrict__ out) {
    unsigned bx = blockIdx.x;
    const float* flow; unsigned lg; size_t toff, ooff;
    if (bx < 32768u)      { flow = fl0; lg = 9; toff = 0ull;        ooff = 0ull; }
    else if (bx < 40960u) { flow = fl1; lg = 8; toff = 67108864ull; ooff = 67108864ull; bx -= 32768u; }
    else if (bx < 43008u) { flow = fl2; lg = 7; toff = 83886080ull; ooff = 83886080ull; bx -= 40960u; }
    else                  { flow = fl3; lg = 6; toff = 88080384ull; ooff = 88080384ull; bx -= 43008u; }

    const unsigned t     = bx * 256u + threadIdx.x;
    const unsigned chalf = t & 1u;
    const unsigned p     = t >> 1;
    const unsigned W     = 1u << lg;
    const unsigned HW    = 1u << (2u * lg);
    const unsigned j     = p & (W - 1u);
    const unsigned i     = (p >> lg) & (W - 1u);
    const unsigned b     = p >> (2u * lg);
    const int      Wi    = (int)W;

    const size_t pixoff = (size_t)i * W + j;
    const float f0 = flow[(size_t)(b * 2u + 0u) * HW + pixoff];
    const float f1 = flow[(size_t)(b * 2u + 1u) * HW + pixoff];

    const float sc = 0.5f * (float)(W - 1u);
    const float x = (float)((int)i - 1) + f0 * sc;   // width coord
    const float y = (float)((int)j - 1) + f1 * sc;   // height coord

    const float x0f = floorf(x);
    const float y0f = floorf(y);
    const int x0 = (int)x0f, x1 = x0 + 1;
    const int y0 = (int)y0f, y1 = y0 + 1;

    // validity folded into weights
    const float wx1 = (x1 >= 0 && x1 < Wi) ? (x - x0f)        : 0.0f;
    const float wx0 = (x0 >= 0 && x0 < Wi) ? (1.0f - (x - x0f)) : 0.0f;
    const float wy1 = (y1 >= 0 && y1 < Wi) ? (y - y0f)        : 0.0f;
    const float wy0 = (y0 >= 0 && y0 < Wi) ? (1.0f - (y - y0f)) : 0.0f;

    const int x0c = min(max(x0, 0), Wi - 1);
    const int x1c = min(max(x1, 0), Wi - 1);
    const int y0c = min(max(y0, 0), Wi - 1);
    const int y1c = min(max(y1, 0), Wi - 1);

    // corner addresses (uint4 = 8 halfs = this thread's channel group)
    const uint4* base = reinterpret_cast<const uint4*>(g_timg + toff)
                        + ((size_t)b * HW) * 2u + chalf;
    const uint4 r00 = __ldg(base + ((size_t)(unsigned)y0c * W + (unsigned)x0c) * 2u);
    const uint4 r01 = __ldg(base + ((size_t)(unsigned)y0c * W + (unsigned)x1c) * 2u);
    const uint4 r10 = __ldg(base + ((size_t)(unsigned)y1c * W + (unsigned)x0c) * 2u);
    const uint4 r11 = __ldg(base + ((size_t)(unsigned)y1c * W + (unsigned)x1c) * 2u);

    const float w00 = wy0 * wx0, w01 = wy0 * wx1;
    const float w10 = wy1 * wx0, w11 = wy1 * wx1;

    float acc[8];
    const unsigned c00[4] = {r00.x, r00.y, r00.z, r00.w};
    const unsigned c01[4] = {r01.x, r01.y, r01.z, r01.w};
    const unsigned c10[4] = {r10.x, r10.y, r10.z, r10.w};
    const unsigned c11[4] = {r11.x, r11.y, r11.z, r11.w};
#pragma unroll
    for (int q = 0; q < 4; q++) {
        float2 v00 = __half22float2(*reinterpret_cast<const __half2*>(&c00[q]));
        float2 v01 = __half22float2(*reinterpret_cast<const __half2*>(&c01[q]));
        float2 v10 = __half22float2(*reinterpret_cast<const __half2*>(&c10[q]));
        float2 v11 = __half22float2(*reinterpret_cast<const __half2*>(&c11[q]));
        acc[2 * q + 0] = w00 * v00.x + w01 * v01.x + w10 * v10.x + w11 * v11.x;
        acc[2 * q + 1] = w00 * v00.y + w01 * v01.y + w10 * v10.y + w11 * v11.y;
    }

    // out layout [B,C,H,W]; this thread's channels are [chalf*8, chalf*8+8).
    const size_t obase = ooff + (size_t)b * 16u * HW + pixoff
                         + (size_t)(chalf * 8u) * HW;
#pragma unroll
    for (int q = 0; q < 8; q++) {
        out[obase + (size_t)q * HW] = acc[q];
    }
}

// ---------------------------------------------------------------------------
// Two launches: transpose (all scales), then gather (all scales).
// Inputs (metadata order): img0, flow0, img1, flow1, img2, flow2, img3, flow3.
// ---------------------------------------------------------------------------
extern "C" void kernel_launch(void* const* d_in, const int* in_sizes, int n_in,
                              void* d_out, int out_size) {
    (void)in_sizes; (void)n_in; (void)out_size;
    const float* im0 = (const float*)d_in[0];
    const float* fl0 = (const float*)d_in[1];
    const float* im1 = (const float*)d_in[2];
    const float* fl1 = (const float*)d_in[3];
    const float* im2 = (const float*)d_in[4];
    const float* fl2 = (const float*)d_in[5];
    const float* im3 = (const float*)d_in[6];
    const float* fl3 = (const float*)d_in[7];
    float* out = (float*)d_out;

    transpose_all<<<43520, 256>>>(im0, im1, im2, im3);
    gather_all<<<43520, 256>>>(fl0, fl1, fl2, fl3, out);
}